// round 2
// baseline (speedup 1.0000x reference)
#include <cuda_runtime.h>

// ----------------------------------------------------------------------------
// Problem constants
// ----------------------------------------------------------------------------
#define BATCH 256
#define SEQ 64
#define NG (BATCH*SEQ)          // 16384 graphs
#define NNODES 17
#define NEDGES 81               // 64 edges + 17 self loops
#define CIN0 3
#define HDIM 128                // HEADS*HID = 2*64
#define LSTM_IN (NNODES*HDIM)   // 2176
#define GATES 512               // 4*128
#define GPB 8                   // graphs per CTA in GAT kernel

#define ALIGN4(x) (((x) + 3) & ~3)   // round float-count up to 16B multiple

// ----------------------------------------------------------------------------
// Scratch (device globals; no allocations allowed). 16B-aligned for float4.
// ----------------------------------------------------------------------------
__device__ __align__(16) float g_bufA[NG * NNODES * HDIM];   // 142.6 MB
__device__ __align__(16) float g_bufB[NG * NNODES * HDIM];   // 142.6 MB
__device__ __align__(16) float g_pre [NG * GATES];           // 33.5 MB
__device__ __align__(16) float g_h1  [NG * HDIM];            // 8.4 MB
__device__ __align__(16) float g_h2  [NG * HDIM];            // 8.4 MB
__device__ __align__(16) float g_hstate[BATCH * HDIM];
__device__ volatile unsigned g_bar_gen;
__device__ unsigned g_bar_cnt;

// ----------------------------------------------------------------------------
// Grid barrier (sense/generation based; safe across graph replays because
// cnt returns to 0 after each barrier and gen advances by equality compare)
// ----------------------------------------------------------------------------
__device__ __forceinline__ void grid_barrier(unsigned nblocks)
{
    __syncthreads();
    if (threadIdx.x == 0) {
        __threadfence();
        unsigned gen = g_bar_gen;
        if (atomicAdd(&g_bar_cnt, 1u) == nblocks - 1u) {
            g_bar_cnt = 0u;
            __threadfence();
            g_bar_gen = gen + 1u;
        } else {
            while (g_bar_gen == gen) { __nanosleep(64); }
        }
    }
    __syncthreads();
}

// ----------------------------------------------------------------------------
// Fused GAT layer: h = attention(h_in @ W) + b, optional ReLU.
// One CTA processes GPB graphs sequentially; W + edge CSR live in smem.
// All float4-accessed smem sections are 16B aligned via ALIGN4 offsets.
// ----------------------------------------------------------------------------
template<int CIN>
__global__ void gat_kernel(const float* __restrict__ x_in, int in_sel, int out_sel,
                           const float* __restrict__ W,
                           const float* __restrict__ a_src,
                           const float* __restrict__ a_dst,
                           const float* __restrict__ bias,
                           const int* __restrict__ edge_index,
                           int relu_flag)
{
    extern __shared__ __align__(16) float smem[];
    // float-offset layout (each float4-read section aligned to 4 floats)
    const int OFF_W   = 0;
    const int OFF_AS  = OFF_W  + CIN * 128;
    const int OFF_AD  = OFF_AS + 128;
    const int OFF_B   = OFF_AD + 128;
    const int OFF_HIN = OFF_B  + 128;
    const int OFF_H   = ALIGN4(OFF_HIN + NNODES * CIN);
    const int OFF_ASN = OFF_H  + NNODES * 128;   // 34
    const int OFF_ADN = OFF_ASN + 34;            // 34
    const int OFF_M   = OFF_ADN + 34;            // 34
    const int OFF_DN  = OFF_M   + 34;            // 34
    const int OFF_EV  = OFF_DN  + 34;            // 162
    const int OFF_INT = ALIGN4(OFF_EV + 162);    // int section

    float* sW   = smem + OFF_W;
    float* sAs  = smem + OFF_AS;
    float* sAd  = smem + OFF_AD;
    float* sB   = smem + OFF_B;
    float* sHin = smem + OFF_HIN;
    float* sH   = smem + OFF_H;
    float* s_as = smem + OFF_ASN;
    float* s_ad = smem + OFF_ADN;
    float* s_m  = smem + OFF_M;
    float* s_dn = smem + OFF_DN;
    float* s_ev = smem + OFF_EV;
    int*   s_src = (int*)(smem + OFF_INT);       // 81
    int*   s_dst = s_src + NEDGES;               // 81
    int*   s_cs  = s_dst + NEDGES;               // 18
    int*   s_ce  = s_cs + NNODES + 1;            // 81

    const int tid = threadIdx.x;

    for (int i = tid; i < CIN * 128; i += blockDim.x) sW[i] = W[i];
    if (tid < 128) { sAs[tid] = a_src[tid]; sAd[tid] = a_dst[tid]; sB[tid] = bias[tid]; }
    if (tid == 0) {
        int cnt[NNODES];
        for (int n = 0; n < NNODES; n++) cnt[n] = 0;
        for (int e = 0; e < NEDGES; e++) {
            int s = (e < 64) ? edge_index[e]      : (e - 64);
            int d = (e < 64) ? edge_index[64 + e] : (e - 64);
            s_src[e] = s; s_dst[e] = d; cnt[d]++;
        }
        int off = 0;
        for (int n = 0; n < NNODES; n++) { s_cs[n] = off; off += cnt[n]; cnt[n] = s_cs[n]; }
        s_cs[NNODES] = off;
        for (int e = 0; e < NEDGES; e++) s_ce[cnt[s_dst[e]]++] = e;
    }
    __syncthreads();

    const float* gin_base = (in_sel == 0) ? x_in : (in_sel == 1 ? g_bufA : g_bufB);
    float* gout_base = (out_sel == 1) ? g_bufA : g_bufB;

    for (int gi = 0; gi < GPB; gi++) {
        const long g = (long)blockIdx.x * GPB + gi;
        const float* hin  = gin_base  + g * (NNODES * CIN);
        float*       hout = gout_base + g * (NNODES * HDIM);

        for (int i = tid; i < NNODES * CIN; i += blockDim.x) sHin[i] = hin[i];
        __syncthreads();

        // h = hin @ W : 17*32 tasks, 4 output cols each (float4 on W rows)
        for (int i = tid; i < NNODES * 32; i += blockDim.x) {
            const int n = i >> 5;
            const int q = (i & 31) << 2;
            float4 acc = make_float4(0.f, 0.f, 0.f, 0.f);
            #pragma unroll 4
            for (int c = 0; c < CIN; c++) {
                const float hv = sHin[n * CIN + c];
                const float4 w = *(const float4*)&sW[c * 128 + q];
                acc.x += hv * w.x; acc.y += hv * w.y;
                acc.z += hv * w.z; acc.w += hv * w.w;
            }
            *(float4*)&sH[n * 128 + q] = acc;
        }
        __syncthreads();

        // per-node attention logits a_s, a_d  (34 tasks)
        if (tid < 34) {
            const int n = tid >> 1, hh = tid & 1;
            const float* hp = &sH[n * 128 + hh * 64];
            float as = 0.f, ad = 0.f;
            #pragma unroll 8
            for (int d = 0; d < 64; d++) {
                as += hp[d] * sAs[hh * 64 + d];
                ad += hp[d] * sAd[hh * 64 + d];
            }
            s_as[tid] = as; s_ad[tid] = ad;
        }
        __syncthreads();

        // edge logits with leaky relu (162 tasks)
        if (tid < 2 * NEDGES) {
            const int e = tid >> 1, hh = tid & 1;
            const float raw = s_as[s_src[e] * 2 + hh] + s_ad[s_dst[e] * 2 + hh];
            s_ev[tid] = raw > 0.f ? raw : 0.2f * raw;
        }
        __syncthreads();

        // per-dst max + denominator (34 tasks)
        if (tid < 34) {
            const int n = tid >> 1, hh = tid & 1;
            float m = -1e30f;
            for (int p = s_cs[n]; p < s_cs[n + 1]; p++)
                m = fmaxf(m, s_ev[s_ce[p] * 2 + hh]);
            float den = 0.f;
            for (int p = s_cs[n]; p < s_cs[n + 1]; p++)
                den += __expf(s_ev[s_ce[p] * 2 + hh] - m);
            s_m[tid] = m; s_dn[tid] = den;
        }
        __syncthreads();

        // alpha (overwrite logits; 162 tasks, elementwise)
        if (tid < 2 * NEDGES) {
            const int e = tid >> 1, hh = tid & 1;
            const int d = s_dst[e];
            s_ev[tid] = __expf(s_ev[tid] - s_m[d * 2 + hh]) / (s_dn[d * 2 + hh] + 1e-16f);
        }
        __syncthreads();

        // aggregate: out[n,:] = sum_{e: dst==n} alpha[e,h] * h[src[e],:]; + bias; relu?
        for (int i = tid; i < NNODES * 32; i += blockDim.x) {
            const int n = i >> 5;
            const int q = (i & 31) << 2;
            const int hh = q >> 6;
            float4 acc = make_float4(0.f, 0.f, 0.f, 0.f);
            for (int p = s_cs[n]; p < s_cs[n + 1]; p++) {
                const int e = s_ce[p];
                const float al = s_ev[e * 2 + hh];
                const float4 hv = *(const float4*)&sH[s_src[e] * 128 + q];
                acc.x += al * hv.x; acc.y += al * hv.y;
                acc.z += al * hv.z; acc.w += al * hv.w;
            }
            const float4 b4 = *(const float4*)&sB[q];
            acc.x += b4.x; acc.y += b4.y; acc.z += b4.z; acc.w += b4.w;
            if (relu_flag) {
                acc.x = fmaxf(acc.x, 0.f); acc.y = fmaxf(acc.y, 0.f);
                acc.z = fmaxf(acc.z, 0.f); acc.w = fmaxf(acc.w, 0.f);
            }
            *(float4*)&hout[n * 128 + q] = acc;
        }
        __syncthreads();
    }
}

// ----------------------------------------------------------------------------
// C[M,N] = A[M,K] @ B[N,K]^T + bias1[N] + bias2[N]
// BM=BN=64, BK=16, 256 threads, 4x4 register tile. M%64==0, N%64==0, K%16==0.
// A selected from device scratch (a_sel: 0 -> g_bufB, 1 -> g_h1); C = g_pre.
// ----------------------------------------------------------------------------
__global__ void gemm_abt(int a_sel, const float* __restrict__ Bmat,
                         const float* __restrict__ bias1, const float* __restrict__ bias2,
                         int M, int Nn, int K)
{
    const float* A = (a_sel == 0) ? g_bufB : g_h1;
    float* C = g_pre;

    __shared__ __align__(16) float As[16][68];   // [k][m], 68-float rows (16B-mult stride)
    __shared__ __align__(16) float Bs[16][68];   // [k][n]

    const int tid = threadIdx.x;
    const int tx = tid & 15, ty = tid >> 4;
    const int bm = blockIdx.x * 64, bn = blockIdx.y * 64;

    float acc[4][4];
    #pragma unroll
    for (int i = 0; i < 4; i++)
        #pragma unroll
        for (int j = 0; j < 4; j++) acc[i][j] = 0.f;

    const int r  = tid >> 2;
    const int kq = (tid & 3) << 2;
    const float* Arow = A    + (long)(bm + r) * K + kq;
    const float* Brow = Bmat + (long)(bn + r) * K + kq;

    for (int k0 = 0; k0 < K; k0 += 16) {
        const float4 av = *(const float4*)(Arow + k0);
        const float4 bv = *(const float4*)(Brow + k0);
        As[kq + 0][r] = av.x; As[kq + 1][r] = av.y; As[kq + 2][r] = av.z; As[kq + 3][r] = av.w;
        Bs[kq + 0][r] = bv.x; Bs[kq + 1][r] = bv.y; Bs[kq + 2][r] = bv.z; Bs[kq + 3][r] = bv.w;
        __syncthreads();
        #pragma unroll
        for (int kk = 0; kk < 16; kk++) {
            const float4 a = *(const float4*)&As[kk][ty << 2];
            const float4 b = *(const float4*)&Bs[kk][tx << 2];
            acc[0][0] += a.x * b.x; acc[0][1] += a.x * b.y; acc[0][2] += a.x * b.z; acc[0][3] += a.x * b.w;
            acc[1][0] += a.y * b.x; acc[1][1] += a.y * b.y; acc[1][2] += a.y * b.z; acc[1][3] += a.y * b.w;
            acc[2][0] += a.z * b.x; acc[2][1] += a.z * b.y; acc[2][2] += a.z * b.z; acc[2][3] += a.z * b.w;
            acc[3][0] += a.w * b.x; acc[3][1] += a.w * b.y; acc[3][2] += a.w * b.z; acc[3][3] += a.w * b.w;
        }
        __syncthreads();
    }

    #pragma unroll
    for (int i = 0; i < 4; i++) {
        const int row = bm + (ty << 2) + i;
        #pragma unroll
        for (int j = 0; j < 4; j++) {
            const int col = bn + (tx << 2) + j;
            C[(long)row * Nn + col] = acc[i][j] + bias1[col] + bias2[col];
        }
    }
}

// ----------------------------------------------------------------------------
// LSTM recurrence (persistent). Grid (32,4): blockIdx.x -> 8 batch rows,
// blockIdx.y -> 32 hidden dims (owns gate rows l, 128+l, 256+l, 384+l).
// whh slice [128 gate rows][128] lives in smem (pad 129 -> conflict-free).
// Pre-gates (x@wih.T + biases) come from g_pre. Cross-CTA h via L2 (__ldcg).
// ----------------------------------------------------------------------------
__global__ void lstm_recur(const float* __restrict__ whh, int out_sel)
{
    extern __shared__ __align__(16) float smem[];
    float* sW = smem;              // 128*129
    float* sH = sW + 128 * 129;    // 8*128
    float* sC = sH + 8 * 128;      // 8*32

    float* hseq = (out_sel == 0) ? g_h1 : g_h2;
    const float* pre = g_pre;

    const int tid = threadIdx.x;
    const int b0 = blockIdx.x * 8;
    const int d0 = blockIdx.y * 32;
    const unsigned nblocks = gridDim.x * gridDim.y;

    // load whh slice: smem row r -> gate j = (r/32)*128 + d0 + (r%32)
    for (int i = tid; i < 128 * 128; i += blockDim.x) {
        const int r = i >> 7, k = i & 127;
        const int j = ((r >> 5) << 7) + d0 + (r & 31);
        sW[r * 129 + k] = whh[j * 128 + k];
    }
    {
        const int row = tid >> 5, l = tid & 31;   // 256 threads exactly
        sC[row * 32 + l] = 0.f;
        g_hstate[(b0 + row) * 128 + d0 + l] = 0.f;
    }
    grid_barrier(nblocks);

    for (int t = 0; t < SEQ; t++) {
        for (int i = tid; i < 8 * 128; i += blockDim.x) {
            const int row = i >> 7, k = i & 127;
            sH[i] = __ldcg(&g_hstate[(b0 + row) * 128 + k]);
        }
        __syncthreads();

        {
            const int row = tid >> 5, l = tid & 31;
            const float* hp = &sH[row * 128];
            const float* w0 = &sW[(l)      * 129];
            const float* w1 = &sW[(32 + l) * 129];
            const float* w2 = &sW[(64 + l) * 129];
            const float* w3 = &sW[(96 + l) * 129];
            const long pbase = ((long)(b0 + row) * SEQ + t) * GATES;
            float a0 = pre[pbase +       d0 + l];
            float a1 = pre[pbase + 128 + d0 + l];
            float a2 = pre[pbase + 256 + d0 + l];
            float a3 = pre[pbase + 384 + d0 + l];
            #pragma unroll 4
            for (int k = 0; k < 128; k++) {
                const float hv = hp[k];
                a0 += hv * w0[k]; a1 += hv * w1[k];
                a2 += hv * w2[k]; a3 += hv * w3[k];
            }
            const float ig = 1.f / (1.f + expf(-a0));
            const float fg = 1.f / (1.f + expf(-a1));
            const float gg = tanhf(a2);
            const float og = 1.f / (1.f + expf(-a3));
            const float c = fg * sC[row * 32 + l] + ig * gg;
            sC[row * 32 + l] = c;
            const float h = og * tanhf(c);
            g_hstate[(b0 + row) * 128 + d0 + l] = h;
            hseq[((long)(b0 + row) * SEQ + t) * 128 + d0 + l] = h;
        }
        grid_barrier(nblocks);
    }
}

// ----------------------------------------------------------------------------
// Temporal attention + FC head. One CTA (128 threads) per batch row.
// ----------------------------------------------------------------------------
__global__ void attn_fc(const float* __restrict__ attn_w, const float* __restrict__ attn_b,
                        const float* __restrict__ fc_w,   const float* __restrict__ fc_b,
                        float* __restrict__ out)
{
    __shared__ float sw[128];
    __shared__ float sc[SEQ];
    __shared__ float sctx[128];

    const int b = blockIdx.x, tid = threadIdx.x;
    const float* h2 = g_h2 + (long)b * SEQ * 128;

    sw[tid] = attn_w[tid];
    __syncthreads();

    if (tid < SEQ) {
        const float* hp = h2 + tid * 128;
        float acc = attn_b[0];
        #pragma unroll 8
        for (int k = 0; k < 128; k++) acc += hp[k] * sw[k];
        sc[tid] = tanhf(acc);
    }
    __syncthreads();

    if (tid == 0) {
        float m = -1e30f;
        for (int t = 0; t < SEQ; t++) m = fmaxf(m, sc[t]);
        float s = 0.f;
        for (int t = 0; t < SEQ; t++) { sc[t] = __expf(sc[t] - m); s += sc[t]; }
        const float inv = 1.f / s;
        for (int t = 0; t < SEQ; t++) sc[t] *= inv;
    }
    __syncthreads();

    {
        float acc = 0.f;
        for (int t = 0; t < SEQ; t++) acc += sc[t] * h2[t * 128 + tid];
        sctx[tid] = acc;
    }
    __syncthreads();

    if (tid < 10) {
        float acc = fc_b[tid];
        #pragma unroll 8
        for (int k = 0; k < 128; k++) acc += sctx[k] * fc_w[tid * 128 + k];
        out[b * 10 + tid] = acc;
    }
}

// ----------------------------------------------------------------------------
// Launcher
// ----------------------------------------------------------------------------
static int gat_smem_bytes(int cin)
{
    int off = cin * 128 + 3 * 128;                 // W + as + ad + b
    off = ALIGN4(off + NNODES * cin);              // + Hin, align for sH
    off += NNODES * 128;                           // sH
    off += 4 * 34 + 162;                           // asn/adn/m/dn/ev
    off = ALIGN4(off);                             // int section
    off += NEDGES * 3 + NNODES + 1;                // src/dst/ce + cs
    return off * 4 + 16;
}

extern "C" void kernel_launch(void* const* d_in, const int* in_sizes, int n_in,
                              void* d_out, int out_size)
{
    const float* x    = (const float*)d_in[0];
    const int*   eidx = (const int*)  d_in[1];
    const float* gw[4]  = { (const float*)d_in[2],  (const float*)d_in[6],
                            (const float*)d_in[10], (const float*)d_in[14] };
    const float* gas[4] = { (const float*)d_in[3],  (const float*)d_in[7],
                            (const float*)d_in[11], (const float*)d_in[15] };
    const float* gad[4] = { (const float*)d_in[4],  (const float*)d_in[8],
                            (const float*)d_in[12], (const float*)d_in[16] };
    const float* gb[4]  = { (const float*)d_in[5],  (const float*)d_in[9],
                            (const float*)d_in[13], (const float*)d_in[17] };
    const float* wih0 = (const float*)d_in[18];
    const float* whh0 = (const float*)d_in[19];
    const float* bih0 = (const float*)d_in[20];
    const float* bhh0 = (const float*)d_in[21];
    const float* wih1 = (const float*)d_in[22];
    const float* whh1 = (const float*)d_in[23];
    const float* bih1 = (const float*)d_in[24];
    const float* bhh1 = (const float*)d_in[25];
    const float* attn_w = (const float*)d_in[26];
    const float* attn_b = (const float*)d_in[27];
    const float* fc_w   = (const float*)d_in[28];
    const float* fc_b   = (const float*)d_in[29];
    float* out = (float*)d_out;

    const int smem_g3   = gat_smem_bytes(CIN0);
    const int smem_g128 = gat_smem_bytes(HDIM);
    const int smem_rec  = (128 * 129 + 8 * 128 + 8 * 32) * 4;

    cudaFuncSetAttribute((const void*)gat_kernel<CIN0>,
                         cudaFuncAttributeMaxDynamicSharedMemorySize, smem_g3);
    cudaFuncSetAttribute((const void*)gat_kernel<HDIM>,
                         cudaFuncAttributeMaxDynamicSharedMemorySize, smem_g128);
    cudaFuncSetAttribute((const void*)lstm_recur,
                         cudaFuncAttributeMaxDynamicSharedMemorySize, smem_rec);

    const int gat_grid = NG / GPB;   // 2048

    // GAT stack: x -> A -> B -> A -> B   (relu on layers 0 and 2)
    gat_kernel<CIN0><<<gat_grid, 256, smem_g3  >>>(x, 0, 1, gw[0], gas[0], gad[0], gb[0], eidx, 1);
    gat_kernel<HDIM><<<gat_grid, 256, smem_g128>>>(nullptr, 1, 2, gw[1], gas[1], gad[1], gb[1], eidx, 0);
    gat_kernel<HDIM><<<gat_grid, 256, smem_g128>>>(nullptr, 2, 1, gw[2], gas[2], gad[2], gb[2], eidx, 1);
    gat_kernel<HDIM><<<gat_grid, 256, smem_g128>>>(nullptr, 1, 2, gw[3], gas[3], gad[3], gb[3], eidx, 0);

    // LSTM layer 0: pre-gates GEMM (lstm_in = g_bufB) then recurrence -> g_h1
    dim3 gemm_grid(NG / 64, GATES / 64);
    gemm_abt<<<gemm_grid, 256>>>(0, wih0, bih0, bhh0, NG, GATES, LSTM_IN);
    lstm_recur<<<dim3(32, 4), 256, smem_rec>>>(whh0, 0);

    // LSTM layer 1: pre-gates GEMM (input = g_h1) then recurrence -> g_h2
    gemm_abt<<<gemm_grid, 256>>>(1, wih1, bih1, bhh1, NG, GATES, HDIM);
    lstm_recur<<<dim3(32, 4), 256, smem_rec>>>(whh1, 1);

    // Attention pooling + FC
    attn_fc<<<BATCH, 128>>>(attn_w, attn_b, fc_w, fc_b, out);
}

// round 3
// speedup vs baseline: 1.4552x; 1.4552x over previous
#include <cuda_runtime.h>

// ----------------------------------------------------------------------------
// Problem constants
// ----------------------------------------------------------------------------
#define BATCH 256
#define SEQ 64
#define NG (BATCH*SEQ)          // 16384 graphs
#define NNODES 17
#define NEDGES 81               // 64 edges + 17 self loops
#define CIN0 3
#define HDIM 128                // HEADS*HID = 2*64
#define GROW (NNODES*HDIM)      // 2176 floats per graph
#define MROWS (NG*NNODES)       // 278528 node rows
#define LSTM_IN 2176
#define GATES 512               // 4*128

#define ALIGN4(x) (((x) + 3) & ~3)

// ----------------------------------------------------------------------------
// Scratch (device globals). 16B-aligned for float4 access.
// ----------------------------------------------------------------------------
__device__ __align__(16) float g_bufA[NG * GROW];    // 142.6 MB
__device__ __align__(16) float g_bufB[NG * GROW];    // 142.6 MB
__device__ __align__(16) float g_tmpH[NG * GROW];    // 142.6 MB (pre-attention H)
__device__ __align__(16) float g_pre [NG * GATES];   // 33.5 MB
__device__ __align__(16) float g_h1  [NG * HDIM];    // 8.4 MB
__device__ __align__(16) float g_h2  [NG * HDIM];    // 8.4 MB
__device__ __align__(16) float g_hstate[BATCH * HDIM];
__device__ volatile unsigned g_bar_gen;
__device__ unsigned g_bar_cnt;

__device__ __forceinline__ const float* bufsel_r(int s)
{
    switch (s) {
        case 0: return g_bufA;
        case 1: return g_bufB;
        case 2: return g_tmpH;
        case 3: return g_h1;
        default: return g_pre;
    }
}
__device__ __forceinline__ float* bufsel_w(int s)
{
    switch (s) {
        case 0: return g_bufA;
        case 1: return g_bufB;
        case 2: return g_tmpH;
        default: return g_pre;
    }
}

// ----------------------------------------------------------------------------
// Grid barrier for the persistent LSTM kernel (128 CTAs < 148 SMs)
// ----------------------------------------------------------------------------
__device__ __forceinline__ void grid_barrier(unsigned nblocks)
{
    __syncthreads();
    if (threadIdx.x == 0) {
        __threadfence();
        unsigned gen = g_bar_gen;
        if (atomicAdd(&g_bar_cnt, 1u) == nblocks - 1u) {
            g_bar_cnt = 0u;
            __threadfence();
            g_bar_gen = gen + 1u;
        } else {
            while (g_bar_gen == gen) { __nanosleep(64); }
        }
    }
    __syncthreads();
}

// ----------------------------------------------------------------------------
// Layer-0 projection: H0[row,128] = x[row,0:3] @ W0[3,128]  (row = graph*17+node)
// ----------------------------------------------------------------------------
__global__ void gat_mm0(const float* __restrict__ x, const float* __restrict__ W)
{
    __shared__ float sW[3 * 128];
    const int tid = threadIdx.x;
    for (int i = tid; i < 3 * 128; i += 256) sW[i] = W[i];
    __syncthreads();

    const long i = (long)blockIdx.x * 256 + tid;
    const long row = i >> 5;
    const int q = ((int)(i & 31)) << 2;
    const float x0 = x[row * 3 + 0];
    const float x1 = x[row * 3 + 1];
    const float x2 = x[row * 3 + 2];
    const float4 w0 = *(const float4*)&sW[0 * 128 + q];
    const float4 w1 = *(const float4*)&sW[1 * 128 + q];
    const float4 w2 = *(const float4*)&sW[2 * 128 + q];
    float4 o;
    o.x = x0 * w0.x + x1 * w1.x + x2 * w2.x;
    o.y = x0 * w0.y + x1 * w1.y + x2 * w2.y;
    o.z = x0 * w0.z + x1 * w1.z + x2 * w2.z;
    o.w = x0 * w0.w + x1 * w1.w + x2 * w2.w;
    *(float4*)&g_tmpH[row * 128 + q] = o;
}

// ----------------------------------------------------------------------------
// 128x128 block SGEMM, 256 threads, 8x8 per thread, BK=16, double-buffered.
// TRANSB=false: C[M,Nn] = A[M,K] @ B[K,Nn]                    (GAT: Nn=128)
// TRANSB=true : C[M,Nn] = A[M,K] @ B[Nn,K]^T + bias1 + bias2  (LSTM pre-gates)
// All dims are multiples of tile sizes (asserted by construction).
// ----------------------------------------------------------------------------
template<bool TRANSB>
__global__ void __launch_bounds__(256, 2)
sgemm128(int a_sel, const float* __restrict__ Bmat,
         const float* __restrict__ bias1, const float* __restrict__ bias2,
         int out_sel, int M, int Nn, int K)
{
    const float* A = bufsel_r(a_sel);
    float* C = bufsel_w(out_sel);

    __shared__ __align__(16) float As[2][16][132];
    __shared__ __align__(16) float Bs[2][16][132];

    const int tid = threadIdx.x;
    const int tx = tid & 15;       // 8-col group
    const int ty = tid >> 4;       // 8-row group
    const int bm = blockIdx.x * 128;
    const int bn = blockIdx.y * 128;

    // A-tile (and transposed-B-tile) load mapping: 128 rows x 16 k
    const int lr = tid >> 1;            // 0..127
    const int lk = (tid & 1) << 3;      // 0 or 8
    const float* Aptr = A + (long)(bm + lr) * K + lk;
    // NN B-tile load mapping: 16 k-rows x 128 cols
    const int wr = tid >> 4;            // 0..15
    const int wc = (tid & 15) << 3;     // 0..120
    const float* Bptr;
    if (TRANSB) Bptr = Bmat + (long)(bn + lr) * K + lk;
    else        Bptr = Bmat + (long)wr * Nn + bn + wc;

    float acc[8][8];
    #pragma unroll
    for (int i = 0; i < 8; i++)
        #pragma unroll
        for (int j = 0; j < 8; j++) acc[i][j] = 0.f;

    const int NT = K >> 4;
    float pa[8], pb[8];

    // prefetch tile 0
    {
        const float4 a0 = *(const float4*)(Aptr);
        const float4 a1 = *(const float4*)(Aptr + 4);
        pa[0]=a0.x; pa[1]=a0.y; pa[2]=a0.z; pa[3]=a0.w;
        pa[4]=a1.x; pa[5]=a1.y; pa[6]=a1.z; pa[7]=a1.w;
        const float4 b0 = *(const float4*)(Bptr);
        const float4 b1 = *(const float4*)(Bptr + 4);
        pb[0]=b0.x; pb[1]=b0.y; pb[2]=b0.z; pb[3]=b0.w;
        pb[4]=b1.x; pb[5]=b1.y; pb[6]=b1.z; pb[7]=b1.w;
    }
    // store tile 0
    #pragma unroll
    for (int i = 0; i < 8; i++) As[0][lk + i][lr] = pa[i];
    if (TRANSB) {
        #pragma unroll
        for (int i = 0; i < 8; i++) Bs[0][lk + i][lr] = pb[i];
    } else {
        *(float4*)&Bs[0][wr][wc]     = make_float4(pb[0], pb[1], pb[2], pb[3]);
        *(float4*)&Bs[0][wr][wc + 4] = make_float4(pb[4], pb[5], pb[6], pb[7]);
    }
    __syncthreads();

    int cur = 0;
    for (int kt = 0; kt < NT; kt++) {
        if (kt + 1 < NT) {
            const long ko = (long)(kt + 1) * 16;
            const float4 a0 = *(const float4*)(Aptr + ko);
            const float4 a1 = *(const float4*)(Aptr + ko + 4);
            pa[0]=a0.x; pa[1]=a0.y; pa[2]=a0.z; pa[3]=a0.w;
            pa[4]=a1.x; pa[5]=a1.y; pa[6]=a1.z; pa[7]=a1.w;
            const float4 b0 = TRANSB ? *(const float4*)(Bptr + ko)
                                     : *(const float4*)(Bptr + ko * Nn);
            const float4 b1 = TRANSB ? *(const float4*)(Bptr + ko + 4)
                                     : *(const float4*)(Bptr + ko * Nn + 4);
            pb[0]=b0.x; pb[1]=b0.y; pb[2]=b0.z; pb[3]=b0.w;
            pb[4]=b1.x; pb[5]=b1.y; pb[6]=b1.z; pb[7]=b1.w;
        }

        #pragma unroll
        for (int kk = 0; kk < 16; kk++) {
            float a[8], b[8];
            const float4 av0 = *(const float4*)&As[cur][kk][ty << 3];
            const float4 av1 = *(const float4*)&As[cur][kk][(ty << 3) + 4];
            a[0]=av0.x; a[1]=av0.y; a[2]=av0.z; a[3]=av0.w;
            a[4]=av1.x; a[5]=av1.y; a[6]=av1.z; a[7]=av1.w;
            const float4 bv0 = *(const float4*)&Bs[cur][kk][tx << 3];
            const float4 bv1 = *(const float4*)&Bs[cur][kk][(tx << 3) + 4];
            b[0]=bv0.x; b[1]=bv0.y; b[2]=bv0.z; b[3]=bv0.w;
            b[4]=bv1.x; b[5]=bv1.y; b[6]=bv1.z; b[7]=bv1.w;
            #pragma unroll
            for (int i = 0; i < 8; i++)
                #pragma unroll
                for (int j = 0; j < 8; j++)
                    acc[i][j] += a[i] * b[j];
        }

        if (kt + 1 < NT) {
            const int nxt = cur ^ 1;
            #pragma unroll
            for (int i = 0; i < 8; i++) As[nxt][lk + i][lr] = pa[i];
            if (TRANSB) {
                #pragma unroll
                for (int i = 0; i < 8; i++) Bs[nxt][lk + i][lr] = pb[i];
            } else {
                *(float4*)&Bs[nxt][wr][wc]     = make_float4(pb[0], pb[1], pb[2], pb[3]);
                *(float4*)&Bs[nxt][wr][wc + 4] = make_float4(pb[4], pb[5], pb[6], pb[7]);
            }
            __syncthreads();
            cur = nxt;
        }
    }

    // epilogue
    #pragma unroll
    for (int i = 0; i < 8; i++) {
        const long row = bm + (ty << 3) + i;
        #pragma unroll
        for (int j = 0; j < 8; j += 4) {
            const int col = bn + (tx << 3) + j;
            float4 v = make_float4(acc[i][j], acc[i][j+1], acc[i][j+2], acc[i][j+3]);
            if (TRANSB) {
                v.x += bias1[col]     + bias2[col];
                v.y += bias1[col + 1] + bias2[col + 1];
                v.z += bias1[col + 2] + bias2[col + 2];
                v.w += bias1[col + 3] + bias2[col + 3];
            }
            *(float4*)&C[row * Nn + col] = v;
        }
    }
}

// ----------------------------------------------------------------------------
// GAT attention + aggregation over H = g_tmpH. 8 graphs per CTA, processed
// IN PARALLEL across all phases. Writes bufsel_w(out_sel).
// ----------------------------------------------------------------------------
__global__ void gat_attn(const float* __restrict__ a_src, const float* __restrict__ a_dst,
                         const float* __restrict__ bias, const int* __restrict__ edge_index,
                         int out_sel, int relu_flag)
{
    extern __shared__ __align__(16) float smem[];
    float* sH   = smem;                    // 8*2176 = 17408
    float* sAs  = sH  + 8 * GROW;          // 128
    float* sAd  = sAs + 128;               // 128
    float* sB   = sAd + 128;               // 128
    float* s_as = sB  + 128;               // 8*34 = 272
    float* s_ad = s_as + 272;
    float* s_m  = s_ad + 272;
    float* s_dn = s_m  + 272;
    float* s_ev = s_dn + 272;              // 8*162 = 1296
    int*   s_src = (int*)(s_ev + 1296);    // 81
    int*   s_dst = s_src + NEDGES;         // 81
    int*   s_cs  = s_dst + NEDGES;         // 18
    int*   s_ce  = s_cs + NNODES + 1;      // 81

    const int tid = threadIdx.x;

    if (tid == 0) {
        int cnt[NNODES];
        for (int n = 0; n < NNODES; n++) cnt[n] = 0;
        for (int e = 0; e < NEDGES; e++) {
            int s = (e < 64) ? edge_index[e]      : (e - 64);
            int d = (e < 64) ? edge_index[64 + e] : (e - 64);
            s_src[e] = s; s_dst[e] = d; cnt[d]++;
        }
        int off = 0;
        for (int n = 0; n < NNODES; n++) { s_cs[n] = off; off += cnt[n]; cnt[n] = s_cs[n]; }
        s_cs[NNODES] = off;
        for (int e = 0; e < NEDGES; e++) s_ce[cnt[s_dst[e]]++] = e;
    }
    if (tid < 128) { sAs[tid] = a_src[tid]; sAd[tid] = a_dst[tid]; sB[tid] = bias[tid]; }

    // load 8 graphs of H (contiguous 17408 floats)
    const float* Hsrc = g_tmpH + (long)blockIdx.x * (8 * GROW);
    for (int i = tid; i < (8 * GROW) / 4; i += 256)
        *(float4*)&sH[i * 4] = *(const float4*)&Hsrc[i * 4];
    __syncthreads();

    // per-node logits a_s, a_d: 8 graphs x 34 (n,head) tasks, padded stride 64
    for (int i = tid; i < 8 * 64; i += 256) {
        const int g = i >> 6, t = i & 63;
        if (t < 34) {
            const int n = t >> 1, hh = t & 1;
            const float* hp = &sH[g * GROW + n * 128 + hh * 64];
            float as = 0.f, ad = 0.f;
            #pragma unroll 8
            for (int d = 0; d < 64; d++) {
                as += hp[d] * sAs[hh * 64 + d];
                ad += hp[d] * sAd[hh * 64 + d];
            }
            s_as[g * 34 + t] = as; s_ad[g * 34 + t] = ad;
        }
    }
    __syncthreads();

    // edge logits (leaky relu): 8 x 162, padded stride 256
    for (int i = tid; i < 8 * 256; i += 256) {
        const int g = i >> 8, t = i & 255;
        if (t < 162) {
            const int e = t >> 1, hh = t & 1;
            const float raw = s_as[g * 34 + s_src[e] * 2 + hh]
                            + s_ad[g * 34 + s_dst[e] * 2 + hh];
            s_ev[g * 162 + t] = raw > 0.f ? raw : 0.2f * raw;
        }
    }
    __syncthreads();

    // per-dst max + denom
    for (int i = tid; i < 8 * 64; i += 256) {
        const int g = i >> 6, t = i & 63;
        if (t < 34) {
            const int n = t >> 1, hh = t & 1;
            float m = -1e30f;
            for (int p = s_cs[n]; p < s_cs[n + 1]; p++)
                m = fmaxf(m, s_ev[g * 162 + s_ce[p] * 2 + hh]);
            float den = 0.f;
            for (int p = s_cs[n]; p < s_cs[n + 1]; p++)
                den += __expf(s_ev[g * 162 + s_ce[p] * 2 + hh] - m);
            s_m[g * 34 + t] = m; s_dn[g * 34 + t] = den;
        }
    }
    __syncthreads();

    // alpha
    for (int i = tid; i < 8 * 256; i += 256) {
        const int g = i >> 8, t = i & 255;
        if (t < 162) {
            const int e = t >> 1, hh = t & 1;
            const int d = s_dst[e];
            s_ev[g * 162 + t] = __expf(s_ev[g * 162 + t] - s_m[g * 34 + d * 2 + hh])
                                / (s_dn[g * 34 + d * 2 + hh] + 1e-16f);
        }
    }
    __syncthreads();

    // aggregate + bias (+relu), write out: 8 x 17 x 32 quad-tasks = 4352
    float* outb = bufsel_w(out_sel);
    for (int i = tid; i < 8 * NNODES * 32; i += 256) {
        const int g = i / (NNODES * 32);
        const int r = i - g * (NNODES * 32);
        const int n = r >> 5;
        const int q = (r & 31) << 2;
        const int hh = q >> 6;
        float4 acc = make_float4(0.f, 0.f, 0.f, 0.f);
        for (int p = s_cs[n]; p < s_cs[n + 1]; p++) {
            const int e = s_ce[p];
            const float al = s_ev[g * 162 + e * 2 + hh];
            const float4 hv = *(const float4*)&sH[g * GROW + s_src[e] * 128 + q];
            acc.x += al * hv.x; acc.y += al * hv.y;
            acc.z += al * hv.z; acc.w += al * hv.w;
        }
        const float4 b4 = *(const float4*)&sB[q];
        acc.x += b4.x; acc.y += b4.y; acc.z += b4.z; acc.w += b4.w;
        if (relu_flag) {
            acc.x = fmaxf(acc.x, 0.f); acc.y = fmaxf(acc.y, 0.f);
            acc.z = fmaxf(acc.z, 0.f); acc.w = fmaxf(acc.w, 0.f);
        }
        *(float4*)&outb[((long)blockIdx.x * 8 + g) * GROW + n * 128 + q] = acc;
    }
}

// ----------------------------------------------------------------------------
// LSTM recurrence (persistent, 128 CTAs). Same as R2 (verified correct).
// ----------------------------------------------------------------------------
__global__ void lstm_recur(const float* __restrict__ whh, int out_sel)
{
    extern __shared__ __align__(16) float smem[];
    float* sW = smem;              // 128*129
    float* sH = sW + 128 * 129;    // 8*128
    float* sC = sH + 8 * 128;      // 8*32

    float* hseq = (out_sel == 0) ? g_h1 : g_h2;
    const float* pre = g_pre;

    const int tid = threadIdx.x;
    const int b0 = blockIdx.x * 8;
    const int d0 = blockIdx.y * 32;
    const unsigned nblocks = gridDim.x * gridDim.y;

    for (int i = tid; i < 128 * 128; i += blockDim.x) {
        const int r = i >> 7, k = i & 127;
        const int j = ((r >> 5) << 7) + d0 + (r & 31);
        sW[r * 129 + k] = whh[j * 128 + k];
    }
    {
        const int row = tid >> 5, l = tid & 31;
        sC[row * 32 + l] = 0.f;
        g_hstate[(b0 + row) * 128 + d0 + l] = 0.f;
    }
    grid_barrier(nblocks);

    for (int t = 0; t < SEQ; t++) {
        for (int i = tid; i < 8 * 128; i += blockDim.x) {
            const int row = i >> 7, k = i & 127;
            sH[i] = __ldcg(&g_hstate[(b0 + row) * 128 + k]);
        }
        __syncthreads();

        {
            const int row = tid >> 5, l = tid & 31;
            const float* hp = &sH[row * 128];
            const float* w0 = &sW[(l)      * 129];
            const float* w1 = &sW[(32 + l) * 129];
            const float* w2 = &sW[(64 + l) * 129];
            const float* w3 = &sW[(96 + l) * 129];
            const long pbase = ((long)(b0 + row) * SEQ + t) * GATES;
            float a0 = pre[pbase +       d0 + l];
            float a1 = pre[pbase + 128 + d0 + l];
            float a2 = pre[pbase + 256 + d0 + l];
            float a3 = pre[pbase + 384 + d0 + l];
            #pragma unroll 4
            for (int k = 0; k < 128; k++) {
                const float hv = hp[k];
                a0 += hv * w0[k]; a1 += hv * w1[k];
                a2 += hv * w2[k]; a3 += hv * w3[k];
            }
            const float ig = 1.f / (1.f + expf(-a0));
            const float fg = 1.f / (1.f + expf(-a1));
            const float gg = tanhf(a2);
            const float og = 1.f / (1.f + expf(-a3));
            const float c = fg * sC[row * 32 + l] + ig * gg;
            sC[row * 32 + l] = c;
            const float h = og * tanhf(c);
            g_hstate[(b0 + row) * 128 + d0 + l] = h;
            hseq[((long)(b0 + row) * SEQ + t) * 128 + d0 + l] = h;
        }
        grid_barrier(nblocks);
    }
}

// ----------------------------------------------------------------------------
// Temporal attention + FC head. One CTA (128 threads) per batch row.
// ----------------------------------------------------------------------------
__global__ void attn_fc(const float* __restrict__ attn_w, const float* __restrict__ attn_b,
                        const float* __restrict__ fc_w,   const float* __restrict__ fc_b,
                        float* __restrict__ out)
{
    __shared__ float sw[128];
    __shared__ float sc[SEQ];
    __shared__ float sctx[128];

    const int b = blockIdx.x, tid = threadIdx.x;
    const float* h2 = g_h2 + (long)b * SEQ * 128;

    sw[tid] = attn_w[tid];
    __syncthreads();

    if (tid < SEQ) {
        const float* hp = h2 + tid * 128;
        float acc = attn_b[0];
        #pragma unroll 8
        for (int k = 0; k < 128; k++) acc += hp[k] * sw[k];
        sc[tid] = tanhf(acc);
    }
    __syncthreads();

    if (tid == 0) {
        float m = -1e30f;
        for (int t = 0; t < SEQ; t++) m = fmaxf(m, sc[t]);
        float s = 0.f;
        for (int t = 0; t < SEQ; t++) { sc[t] = __expf(sc[t] - m); s += sc[t]; }
        const float inv = 1.f / s;
        for (int t = 0; t < SEQ; t++) sc[t] *= inv;
    }
    __syncthreads();

    {
        float acc = 0.f;
        for (int t = 0; t < SEQ; t++) acc += sc[t] * h2[t * 128 + tid];
        sctx[tid] = acc;
    }
    __syncthreads();

    if (tid < 10) {
        float acc = fc_b[tid];
        #pragma unroll 8
        for (int k = 0; k < 128; k++) acc += sctx[k] * fc_w[tid * 128 + k];
        out[b * 10 + tid] = acc;
    }
}

// ----------------------------------------------------------------------------
// Launcher
// ----------------------------------------------------------------------------
extern "C" void kernel_launch(void* const* d_in, const int* in_sizes, int n_in,
                              void* d_out, int out_size)
{
    const float* x    = (const float*)d_in[0];
    const int*   eidx = (const int*)  d_in[1];
    const float* gw[4]  = { (const float*)d_in[2],  (const float*)d_in[6],
                            (const float*)d_in[10], (const float*)d_in[14] };
    const float* gas[4] = { (const float*)d_in[3],  (const float*)d_in[7],
                            (const float*)d_in[11], (const float*)d_in[15] };
    const float* gad[4] = { (const float*)d_in[4],  (const float*)d_in[8],
                            (const float*)d_in[12], (const float*)d_in[16] };
    const float* gb[4]  = { (const float*)d_in[5],  (const float*)d_in[9],
                            (const float*)d_in[13], (const float*)d_in[17] };
    const float* wih0 = (const float*)d_in[18];
    const float* whh0 = (const float*)d_in[19];
    const float* bih0 = (const float*)d_in[20];
    const float* bhh0 = (const float*)d_in[21];
    const float* wih1 = (const float*)d_in[22];
    const float* whh1 = (const float*)d_in[23];
    const float* bih1 = (const float*)d_in[24];
    const float* bhh1 = (const float*)d_in[25];
    const float* attn_w = (const float*)d_in[26];
    const float* attn_b = (const float*)d_in[27];
    const float* fc_w   = (const float*)d_in[28];
    const float* fc_b   = (const float*)d_in[29];
    float* out = (float*)d_out;

    // smem sizes
    const int smem_attn = ((8 * GROW + 3 * 128 + 4 * 272 + 1296) +
                           (NEDGES * 3 + NNODES + 1 + 4)) * 4;
    const int smem_rec  = (128 * 129 + 8 * 128 + 8 * 32) * 4;

    cudaFuncSetAttribute((const void*)gat_attn,
                         cudaFuncAttributeMaxDynamicSharedMemorySize, smem_attn);
    cudaFuncSetAttribute((const void*)lstm_recur,
                         cudaFuncAttributeMaxDynamicSharedMemorySize, smem_rec);

    const int attn_grid = NG / 8;        // 2048
    const int mm_grid   = MROWS / 128;   // 2176

    // ---- GAT layer 0: x @ W0 -> tmpH -> attn -> bufA (relu)
    gat_mm0<<<(MROWS * 32) / 256, 256>>>(x, gw[0]);
    gat_attn<<<attn_grid, 256, smem_attn>>>(gas[0], gad[0], gb[0], eidx, 0, 1);

    // ---- GAT layer 1: bufA @ W1 -> tmpH -> attn -> bufB
    sgemm128<false><<<dim3(mm_grid, 1), 256>>>(0, gw[1], nullptr, nullptr, 2, MROWS, 128, 128);
    gat_attn<<<attn_grid, 256, smem_attn>>>(gas[1], gad[1], gb[1], eidx, 1, 0);

    // ---- GAT layer 2: bufB @ W2 -> tmpH -> attn -> bufA (relu)
    sgemm128<false><<<dim3(mm_grid, 1), 256>>>(1, gw[2], nullptr, nullptr, 2, MROWS, 128, 128);
    gat_attn<<<attn_grid, 256, smem_attn>>>(gas[2], gad[2], gb[2], eidx, 0, 1);

    // ---- GAT layer 3: bufA @ W3 -> tmpH -> attn -> bufB
    sgemm128<false><<<dim3(mm_grid, 1), 256>>>(0, gw[3], nullptr, nullptr, 2, MROWS, 128, 128);
    gat_attn<<<attn_grid, 256, smem_attn>>>(gas[3], gad[3], gb[3], eidx, 1, 0);

    // ---- LSTM layer 0: pre-gates GEMM (A = bufB viewed [16384, 2176]) + recurrence
    sgemm128<true><<<dim3(NG / 128, GATES / 128), 256>>>(1, wih0, bih0, bhh0, 3 + 1, NG, GATES, LSTM_IN);
    lstm_recur<<<dim3(32, 4), 256, smem_rec>>>(whh0, 0);

    // ---- LSTM layer 1: pre-gates GEMM (A = g_h1 [16384,128]) + recurrence
    sgemm128<true><<<dim3(NG / 128, GATES / 128), 256>>>(3, wih1, bih1, bhh1, 3 + 1, NG, GATES, HDIM);
    lstm_recur<<<dim3(32, 4), 256, smem_rec>>>(whh1, 1);

    // ---- head
    attn_fc<<<BATCH, 128>>>(attn_w, attn_b, fc_w, fc_b, out);
}